// round 17
// baseline (speedup 1.0000x reference)
#include <cuda_runtime.h>
#include <cuda_fp16.h>
#include <cstdint>

#define B_   16
#define N_   4096
#define C_   64
#define S_   1024
#define K0_  16
#define K1_  32
#define M0_  (B_ * S_ * K0_)   // 262144
#define M1_  (B_ * S_ * K1_)   // 524288
#define R0SQ 0.01f
#define R1SQ 0.04f
#define EPS_ 1e-5f

// ---------------- scratch (device globals) ----------------
__device__ __half g_fp0[B_ * N_ * C_];     // F' scale 0, fp16
__device__ __half g_fp1[B_ * N_ * C_];     // F' scale 1, fp16
__device__ int    g_idx0[B_ * S_ * K0_];
__device__ int    g_idx1[B_ * S_ * K1_];
__device__ __half g_b0[64u * 262144u];     // s0 layer1 out
__device__ __half g_b1[96u * 524288u];     // s1 layer1 out
__device__ float  g_gmx0[16384u * 128u];
__device__ float  g_gmn0[16384u * 128u];
__device__ float  g_gmx1[16384u * 128u];
__device__ float  g_gmn1[16384u * 128u];
__device__ float  g_stats6[6 * 256];       // 6 layers x (128 sum, 128 sumsq)

__device__ __forceinline__ void mma_tf32(float* d, const uint32_t* a, const uint32_t* b) {
    asm volatile("mma.sync.aligned.m16n8k8.row.col.f32.tf32.tf32.f32 "
                 "{%0,%1,%2,%3}, {%4,%5,%6,%7}, {%8,%9}, {%0,%1,%2,%3};"
                 : "+f"(d[0]), "+f"(d[1]), "+f"(d[2]), "+f"(d[3])
                 : "r"(a[0]), "r"(a[1]), "r"(a[2]), "r"(a[3]), "r"(b[0]), "r"(b[1]));
}

// ---------------- zero stats ----------------
__global__ void zero6_kernel() {
    for (int i = threadIdx.x; i < 6 * 256; i += 256) g_stats6[i] = 0.0f;
}

// ---------------- FPS (redux-based reduction) ----------------
__global__ void fps_kernel(const float* __restrict__ xyz, float* __restrict__ newxyz)
{
    extern __shared__ float sm[];
    float* sx = sm; float* sy = sm + N_; float* sz = sm + 2 * N_;
    __shared__ unsigned sbits[2][32];
    __shared__ int      sidx[2][32];

    const int b = blockIdx.x;
    const int t = threadIdx.x;          // 1024
    const int lane = t & 31, wid = t >> 5;

    for (int i = t; i < N_; i += 1024) {
        const float* p = xyz + ((size_t)b * N_ + i) * 3;
        sx[i] = p[0]; sy[i] = p[1]; sz[i] = p[2];
    }
    __syncthreads();

    float px[4], py[4], pz[4], dist[4];
#pragma unroll
    for (int j = 0; j < 4; ++j) {
        int n = t + (j << 10);
        px[j] = sx[n]; py[j] = sy[n]; pz[j] = sz[n];
        dist[j] = 1e10f;
    }

    if (t == 0) {
        float* o = newxyz + (size_t)b * S_ * 3;
        o[0] = sx[0]; o[1] = sy[0]; o[2] = sz[0];
    }
    float lx = sx[0], ly = sy[0], lz = sz[0];

    int p_ = 0;
    for (int i = 1; i < S_; ++i) {
        float bv = -1.0f; int bi = 0;
#pragma unroll
        for (int j = 0; j < 4; ++j) {
            float dx = px[j] - lx, dy = py[j] - ly, dz = pz[j] - lz;
            float d = dx * dx + dy * dy + dz * dz;
            float nd = fminf(dist[j], d);
            dist[j] = nd;
            if (nd > bv) { bv = nd; bi = t + (j << 10); }
        }
        unsigned dbits = __float_as_uint(bv);
        unsigned wmax = __reduce_max_sync(0xffffffffu, dbits);
        unsigned cand = (dbits == wmax) ? (unsigned)bi : 0xffffffffu;
        unsigned widx = __reduce_min_sync(0xffffffffu, cand);
        if (lane == 0) { sbits[p_][wid] = wmax; sidx[p_][wid] = (int)widx; }
        __syncthreads();
        unsigned vb = sbits[p_][lane];
        int      vi = sidx[p_][lane];
        unsigned bmax = __reduce_max_sync(0xffffffffu, vb);
        unsigned c2 = (vb == bmax) ? (unsigned)vi : 0xffffffffu;
        int bsel = (int)__reduce_min_sync(0xffffffffu, c2);
        lx = sx[bsel]; ly = sy[bsel]; lz = sz[bsel];
        if (t == 0) {
            float* o = newxyz + ((size_t)b * S_ + i) * 3;
            o[0] = lx; o[1] = ly; o[2] = lz;
        }
        p_ ^= 1;
    }
}

// ---------------- combined feature pre-GEMM -> fp16 F' ----------------
__global__ __launch_bounds__(256) void featgemm2_kernel(
    const float* __restrict__ feat,
    const float* __restrict__ W0, const float* __restrict__ W1,
    __half* __restrict__ Fp0, __half* __restrict__ Fp1)
{
    extern __shared__ float sm[];
    float* Wt = sm;             // [64][65]
    float* Xs = Wt + 64 * 65;   // [64][128]
    const int tid = threadIdx.x;
    const int b = blockIdx.y;
    const int n0 = blockIdx.x * 128;

    for (int i = tid; i < 64 * 32; i += 256) {
        int k = i >> 5, q = i & 31;
        *(float4*)(Xs + k * 128 + q * 4) =
            *(const float4*)(feat + ((size_t)(b * 64 + k)) * N_ + n0 + q * 4);
    }

    const int mi = tid & 15, ci = tid >> 4;
#pragma unroll
    for (int s = 0; s < 2; ++s) {
        const float* W = s ? W1 : W0;
        __half* Fp = s ? Fp1 : Fp0;
        __syncthreads();
        for (int i = tid; i < 64 * 64; i += 256) {
            int co = i >> 6, k = i & 63;
            Wt[k * 65 + co] = W[co * 67 + 3 + k];
        }
        __syncthreads();

        float acc[4][8];
#pragma unroll
        for (int j = 0; j < 4; ++j)
#pragma unroll
            for (int r = 0; r < 8; ++r) acc[j][r] = 0.0f;

#pragma unroll 4
        for (int k = 0; k < 64; ++k) {
            float xf[8];
            *(float4*)xf       = *(const float4*)(Xs + k * 128 + mi * 8);
            *(float4*)(xf + 4) = *(const float4*)(Xs + k * 128 + mi * 8 + 4);
#pragma unroll
            for (int j = 0; j < 4; ++j) {
                float w = Wt[k * 65 + ci * 4 + j];
#pragma unroll
                for (int r = 0; r < 8; ++r) acc[j][r] = fmaf(w, xf[r], acc[j][r]);
            }
        }
#pragma unroll
        for (int r = 0; r < 8; ++r) {
            size_t row = (size_t)(b << 12) + n0 + mi * 8 + r;
            __half2 h0 = __floats2half2_rn(acc[0][r], acc[1][r]);
            __half2 h1 = __floats2half2_rn(acc[2][r], acc[3][r]);
            uint2 u = make_uint2(*(uint32_t*)&h0, *(uint32_t*)&h1);
            *(uint2*)(Fp + (row << 6) + ci * 4) = u;
        }
    }
}

// ---------------- single-radius ball query: one center per warp ----------------
template <int KK>
__global__ void ballquery1_kernel(const float* __restrict__ xyz,
                                  const float* __restrict__ newxyz,
                                  int* __restrict__ idx, float rsq)
{
    __shared__ float sx[N_], sy[N_], sz[N_];
    const int bb = blockIdx.y;
    const int tid = threadIdx.x;                 // 512
    const int lane = tid & 31, w = tid >> 5;     // 16 warps = 16 centers

    for (int i = tid; i < N_ * 3; i += 512) {
        float v = xyz[(size_t)bb * N_ * 3 + i];
        int n = i / 3, d = i - n * 3;
        if (d == 0) sx[n] = v; else if (d == 1) sy[n] = v; else sz[n] = v;
    }
    __syncthreads();

    const unsigned ltmask = (1u << lane) - 1u;

    const int s_ = blockIdx.x * 16 + w;
    const float* ctr = newxyz + ((size_t)bb * S_ + s_) * 3;
    float cx = ctr[0], cy = ctr[1], cz = ctr[2];
    int* o = idx + ((size_t)bb * S_ + s_) * KK;
    int cnt = 0, first = 0;

    for (int base = 0; base < N_; base += 32) {
        int n = base + lane;
        float dx = sx[n] - cx, dy = sy[n] - cy, dz = sz[n] - cz;
        float d2 = dx * dx + dy * dy + dz * dz;
        unsigned m = __ballot_sync(0xffffffffu, d2 < rsq);
        if (m) {
            if (cnt == 0) first = base + __ffs(m) - 1;
            int pos = cnt + __popc(m & ltmask);
            if ((d2 < rsq) && pos < KK) o[pos] = n;
            cnt += __popc(m);
            if (cnt >= KK) break;
        }
    }
    if (cnt > KK) cnt = KK;
    for (int pos = cnt + lane; pos < KK; pos += 32) o[pos] = first;
}

// ---------------- layer-0 stats only (gather, fp32 BN stats, no Y write) ----------------
template <int K>
__global__ __launch_bounds__(256) void stats0_kernel(
    const float* __restrict__ xyz, const float* __restrict__ newxyz,
    const __half* __restrict__ Fp, const float* __restrict__ W /*64x67*/,
    const int* __restrict__ idx, float* __restrict__ stats)
{
    constexpr int LK = (K == 16) ? 4 : 5;
    __shared__ float sms[64 * 132];
    __shared__ float swx[64], swy[64], swz[64];
    const int tid = threadIdx.x;
    const size_t m0 = (size_t)blockIdx.x * 128;

    if (tid < 64) {
        swx[tid] = W[tid * 67 + 0];
        swy[tid] = W[tid * 67 + 1];
        swz[tid] = W[tid * 67 + 2];
    }
    __syncthreads();

    {
        const int mloc = tid >> 1, half = tid & 1;
        const size_t m = m0 + mloc;
        const int n = idx[m];
        const int sflat = (int)(m >> LK);
        const int b = sflat >> 10;
        const float* ctr = newxyz + (size_t)sflat * 3;
        const float* p = xyz + ((size_t)(b << 12) + n) * 3;
        const float rx = p[0] - ctr[0], ry = p[1] - ctr[1], rz = p[2] - ctr[2];
        const uint4* f = (const uint4*)(Fp + (((size_t)(b << 12) + n) << 6) + half * 32);
#pragma unroll
        for (int q4 = 0; q4 < 4; ++q4) {
            uint4 u = f[q4];
            __half2 h0 = *(__half2*)&u.x;
            __half2 h1 = *(__half2*)&u.y;
            __half2 h2 = *(__half2*)&u.z;
            __half2 h3 = *(__half2*)&u.w;
            int c = half * 32 + q4 * 8;
            sms[(c + 0) * 132 + mloc] = fmaf(swx[c + 0], rx, fmaf(swy[c + 0], ry, fmaf(swz[c + 0], rz, __low2float(h0))));
            sms[(c + 1) * 132 + mloc] = fmaf(swx[c + 1], rx, fmaf(swy[c + 1], ry, fmaf(swz[c + 1], rz, __high2float(h0))));
            sms[(c + 2) * 132 + mloc] = fmaf(swx[c + 2], rx, fmaf(swy[c + 2], ry, fmaf(swz[c + 2], rz, __low2float(h1))));
            sms[(c + 3) * 132 + mloc] = fmaf(swx[c + 3], rx, fmaf(swy[c + 3], ry, fmaf(swz[c + 3], rz, __high2float(h1))));
            sms[(c + 4) * 132 + mloc] = fmaf(swx[c + 4], rx, fmaf(swy[c + 4], ry, fmaf(swz[c + 4], rz, __low2float(h2))));
            sms[(c + 5) * 132 + mloc] = fmaf(swx[c + 5], rx, fmaf(swy[c + 5], ry, fmaf(swz[c + 5], rz, __high2float(h2))));
            sms[(c + 6) * 132 + mloc] = fmaf(swx[c + 6], rx, fmaf(swy[c + 6], ry, fmaf(swz[c + 6], rz, __low2float(h3))));
            sms[(c + 7) * 132 + mloc] = fmaf(swx[c + 7], rx, fmaf(swy[c + 7], ry, fmaf(swz[c + 7], rz, __high2float(h3))));
        }
    }
    __syncthreads();

    {
        const int c = tid >> 2, part = tid & 3;
        float s = 0.0f, s2 = 0.0f;
        const float4* row = (const float4*)(sms + c * 132 + part * 32);
#pragma unroll
        for (int q = 0; q < 8; ++q) {
            float4 v = row[q];
            s  += v.x + v.y + v.z + v.w;
            s2 += v.x * v.x + v.y * v.y + v.z * v.z + v.w * v.w;
        }
        s  += __shfl_down_sync(0xffffffffu, s, 2);
        s  += __shfl_down_sync(0xffffffffu, s, 1);
        s2 += __shfl_down_sync(0xffffffffu, s2, 2);
        s2 += __shfl_down_sync(0xffffffffu, s2, 1);
        if (part == 0) {
            atomicAdd(&stats[c], s);
            atomicAdd(&stats[128 + c], s2);
        }
    }
}

// ---------------- layer-1 mma with fused gather (CIN=64), fp16 smem staging ----------------
template <int COUT, int K>
__global__ __launch_bounds__(256) void mma_gather_kernel(
    const float* __restrict__ xyz, const float* __restrict__ newxyz,
    const __half* __restrict__ Fp, const float* __restrict__ W0 /*64x67*/,
    const int* __restrict__ idx, const float* __restrict__ W /*COUTx64*/,
    __half* __restrict__ Y,
    const float* __restrict__ stats_in, const float* __restrict__ gam,
    const float* __restrict__ bet, float invM, float* __restrict__ stats_out)
{
    constexpr int CIN = 64;
    constexpr int LK = (K == 16) ? 4 : 5;
    constexpr int WCT = COUT / 16;
    constexpr int XPh = CIN + 8;
    constexpr int WPh = COUT + 8;
    extern __shared__ char smc[];
    __half* Wt  = (__half*)smc;                        // [CIN][WPh]
    __half* Xs  = (__half*)(smc + CIN * WPh * 2);      // [128][XPh]
    float*  red = (float*)(smc + CIN * WPh * 2 + 128 * XPh * 2);  // [2*COUT]
    __shared__ float saff[256];
    __shared__ float swx[64], swy[64], swz[64];
    const int tid = threadIdx.x;
    const size_t m0 = (size_t)blockIdx.x * 128;

    if (tid < CIN) {
        float mean = stats_in[tid] * invM;
        float var  = stats_in[128 + tid] * invM - mean * mean;
        float a = gam[tid] * rsqrtf(var + EPS_);
        saff[tid] = a;
        saff[128 + tid] = bet[tid] - mean * a;
    } else if (tid < 128) {
        int c = tid - 64;
        swx[c] = W0[c * 67 + 0];
        swy[c] = W0[c * 67 + 1];
        swz[c] = W0[c * 67 + 2];
    } else if (tid < 192) {
        int c = tid - 128;
        swx[c + 0] = swx[c + 0];  // no-op filler (avoid divergence cost)
    }
    if (tid >= 128 && tid < 192) {
        int c = tid - 128;
        swx[c] = W0[c * 67 + 0];  // redundant-safe rewrite (same value)
    }
    if (tid < 64) {
        swx[tid] = W0[tid * 67 + 0];
        swy[tid] = W0[tid * 67 + 1];
        swz[tid] = W0[tid * 67 + 2];
    }
    if (tid < 2 * COUT) red[tid] = 0.0f;

    for (int i = tid; i < CIN * COUT; i += 256) {
        int co = i / CIN, k = i - co * CIN;
        Wt[k * WPh + co] = __float2half_rn(W[i]);
    }
    __syncthreads();   // saff + swx/y/z ready

    // gather-stage X: 2 threads per row
    {
        const int mloc = tid >> 1, half = tid & 1;
        const size_t m = m0 + mloc;
        const int n = idx[m];
        const int sflat = (int)(m >> LK);
        const int b = sflat >> 10;
        const float* ctr = newxyz + (size_t)sflat * 3;
        const float* p = xyz + ((size_t)(b << 12) + n) * 3;
        const float rx = p[0] - ctr[0], ry = p[1] - ctr[1], rz = p[2] - ctr[2];
        const uint4* f = (const uint4*)(Fp + (((size_t)(b << 12) + n) << 6) + half * 32);
#pragma unroll
        for (int q4 = 0; q4 < 4; ++q4) {
            uint4 u = f[q4];
            __half2 h0 = *(__half2*)&u.x;
            __half2 h1 = *(__half2*)&u.y;
            __half2 h2 = *(__half2*)&u.z;
            __half2 h3 = *(__half2*)&u.w;
            int c = half * 32 + q4 * 8;
            float o[8];
            o[0] = fmaf(swx[c + 0], rx, fmaf(swy[c + 0], ry, fmaf(swz[c + 0], rz, __low2float(h0))));
            o[1] = fmaf(swx[c + 1], rx, fmaf(swy[c + 1], ry, fmaf(swz[c + 1], rz, __high2float(h0))));
            o[2] = fmaf(swx[c + 2], rx, fmaf(swy[c + 2], ry, fmaf(swz[c + 2], rz, __low2float(h1))));
            o[3] = fmaf(swx[c + 3], rx, fmaf(swy[c + 3], ry, fmaf(swz[c + 3], rz, __high2float(h1))));
            o[4] = fmaf(swx[c + 4], rx, fmaf(swy[c + 4], ry, fmaf(swz[c + 4], rz, __low2float(h2))));
            o[5] = fmaf(swx[c + 5], rx, fmaf(swy[c + 5], ry, fmaf(swz[c + 5], rz, __high2float(h2))));
            o[6] = fmaf(swx[c + 6], rx, fmaf(swy[c + 6], ry, fmaf(swz[c + 6], rz, __low2float(h3))));
            o[7] = fmaf(swx[c + 7], rx, fmaf(swy[c + 7], ry, fmaf(swz[c + 7], rz, __high2float(h3))));
            // affine + relu + pack fp16
            uint32_t pw[4];
#pragma unroll
            for (int pq = 0; pq < 4; ++pq) {
                int cc = c + 2 * pq;
                float e0 = fmaxf(fmaf(o[2 * pq],     saff[cc],     saff[128 + cc]),     0.0f);
                float e1 = fmaxf(fmaf(o[2 * pq + 1], saff[cc + 1], saff[128 + cc + 1]), 0.0f);
                __half2 hh = __floats2half2_rn(e0, e1);
                pw[pq] = *(uint32_t*)&hh;
            }
            *(uint4*)(Xs + mloc * XPh + c) = make_uint4(pw[0], pw[1], pw[2], pw[3]);
        }
    }
    __syncthreads();

    const int lane = tid & 31, w = tid >> 5;
    const int gid = lane >> 2, tig = lane & 3;
    const int wm = (w & 3) * 32;
    const int wc = (w >> 2) * (COUT / 2);

    float acc[2][WCT][4];
#pragma unroll
    for (int mt = 0; mt < 2; ++mt)
#pragma unroll
        for (int ct = 0; ct < WCT; ++ct)
#pragma unroll
            for (int r = 0; r < 4; ++r) acc[mt][ct][r] = 0.0f;

#pragma unroll
    for (int k0 = 0; k0 < CIN; k0 += 8) {
        uint32_t a[2][4];
#pragma unroll
        for (int mt = 0; mt < 2; ++mt) {
            int r = wm + mt * 16 + gid;
            a[mt][0] = __float_as_uint(__half2float(Xs[r * XPh + k0 + tig]));
            a[mt][1] = __float_as_uint(__half2float(Xs[(r + 8) * XPh + k0 + tig]));
            a[mt][2] = __float_as_uint(__half2float(Xs[r * XPh + k0 + tig + 4]));
            a[mt][3] = __float_as_uint(__half2float(Xs[(r + 8) * XPh + k0 + tig + 4]));
        }
        uint32_t bf[WCT][2];
#pragma unroll
        for (int ct = 0; ct < WCT; ++ct) {
            int co = wc + ct * 8 + gid;
            bf[ct][0] = __float_as_uint(__half2float(Wt[(k0 + tig) * WPh + co]));
            bf[ct][1] = __float_as_uint(__half2float(Wt[(k0 + tig + 4) * WPh + co]));
        }
#pragma unroll
        for (int mt = 0; mt < 2; ++mt)
#pragma unroll
            for (int ct = 0; ct < WCT; ++ct)
                mma_tf32(acc[mt][ct], a[mt], bf[ct]);
    }

#pragma unroll
    for (int ct = 0; ct < WCT; ++ct) {
        float se = 0, so = 0, qe = 0, qo = 0;
#pragma unroll
        for (int mt = 0; mt < 2; ++mt) {
            const float* d = acc[mt][ct];
            se += d[0] + d[2]; so += d[1] + d[3];
            qe += d[0] * d[0] + d[2] * d[2];
            qo += d[1] * d[1] + d[3] * d[3];
        }
#pragma unroll
        for (int off = 16; off >= 4; off >>= 1) {
            se += __shfl_down_sync(0xffffffffu, se, off);
            so += __shfl_down_sync(0xffffffffu, so, off);
            qe += __shfl_down_sync(0xffffffffu, qe, off);
            qo += __shfl_down_sync(0xffffffffu, qo, off);
        }
        if (gid == 0) {
            int co = wc + ct * 8 + tig * 2;
            atomicAdd(&red[co], se);
            atomicAdd(&red[co + 1], so);
            atomicAdd(&red[COUT + co], qe);
            atomicAdd(&red[COUT + co + 1], qo);
        }
    }

#pragma unroll
    for (int mt = 0; mt < 2; ++mt)
#pragma unroll
        for (int ct = 0; ct < WCT; ++ct) {
            size_t m = m0 + wm + mt * 16 + gid;
            int co = wc + ct * 8 + tig * 2;
            const float* d = acc[mt][ct];
            __half2 h0 = __floats2half2_rn(d[0], d[1]);
            __half2 h1 = __floats2half2_rn(d[2], d[3]);
            *(__half2*)(Y + m * COUT + co)       = h0;
            *(__half2*)(Y + (m + 8) * COUT + co) = h1;
        }

    __syncthreads();
    if (tid < COUT) atomicAdd(&stats_out[tid], red[tid]);
    else if (tid < 2 * COUT) atomicAdd(&stats_out[128 + (tid - COUT)], red[tid]);
}

// ---------------- layer-2 tf32 MMA (fp16 staging) + pool epilogue ----------------
template <int CIN, int COUT, int POOLK>
__global__ __launch_bounds__(256) void mma_kernel(
    const __half* __restrict__ X, const float* __restrict__ W,
    float* __restrict__ gmx, float* __restrict__ gmn,
    const float* __restrict__ stats_in, const float* __restrict__ gam,
    const float* __restrict__ bet, float invM, float* __restrict__ stats_out)
{
    constexpr int WCT = COUT / 16;
    constexpr int XPh = CIN + 8;
    constexpr int WPh = COUT + 8;
    extern __shared__ char smc[];
    __half* Wt  = (__half*)smc;
    __half* Xs  = (__half*)(smc + CIN * WPh * 2);
    float*  red = (float*)(smc + CIN * WPh * 2 + 128 * XPh * 2);
    __shared__ float saff[256];
    const int tid = threadIdx.x;
    const size_t m0 = (size_t)blockIdx.x * 128;

    if (tid < CIN) {
        float mean = stats_in[tid] * invM;
        float var  = stats_in[128 + tid] * invM - mean * mean;
        float a = gam[tid] * rsqrtf(var + EPS_);
        saff[tid] = a;
        saff[128 + tid] = bet[tid] - mean * a;
    }
    if (tid < 2 * COUT) red[tid] = 0.0f;

    for (int i = tid; i < CIN * COUT; i += 256) {
        int co = i / CIN, k = i - co * CIN;
        Wt[k * WPh + co] = __float2half_rn(W[i]);
    }
    __syncthreads();

    for (int i = tid; i < 128 * (CIN / 4); i += 256) {
        int row = i / (CIN / 4), c4 = i % (CIN / 4);
        int c = c4 * 4;
        uint2 u = *(const uint2*)(X + (m0 + row) * CIN + c);
        __half2 h0 = *(__half2*)&u.x;
        __half2 h1 = *(__half2*)&u.y;
        float e0 = fmaxf(fmaf(__low2float(h0),  saff[c + 0], saff[128 + c + 0]), 0.0f);
        float e1 = fmaxf(fmaf(__high2float(h0), saff[c + 1], saff[128 + c + 1]), 0.0f);
        float e2 = fmaxf(fmaf(__low2float(h1),  saff[c + 2], saff[128 + c + 2]), 0.0f);
        float e3 = fmaxf(fmaf(__high2float(h1), saff[c + 3], saff[128 + c + 3]), 0.0f);
        __half2 o0 = __floats2half2_rn(e0, e1);
        __half2 o1 = __floats2half2_rn(e2, e3);
        *(uint2*)(Xs + row * XPh + c) = make_uint2(*(uint32_t*)&o0, *(uint32_t*)&o1);
    }
    __syncthreads();

    const int lane = tid & 31, w = tid >> 5;
    const int gid = lane >> 2, tig = lane & 3;
    const int wm = (w & 3) * 32;
    const int wc = (w >> 2) * (COUT / 2);

    float acc[2][WCT][4];
#pragma unroll
    for (int mt = 0; mt < 2; ++mt)
#pragma unroll
        for (int ct = 0; ct < WCT; ++ct)
#pragma unroll
            for (int r = 0; r < 4; ++r) acc[mt][ct][r] = 0.0f;

#pragma unroll
    for (int k0 = 0; k0 < CIN; k0 += 8) {
        uint32_t a[2][4];
#pragma unroll
        for (int mt = 0; mt < 2; ++mt) {
            int r = wm + mt * 16 + gid;
            a[mt][0] = __float_as_uint(__half2float(Xs[r * XPh + k0 + tig]));
            a[mt][1] = __float_as_uint(__half2float(Xs[(r + 8) * XPh + k0 + tig]));
            a[mt][2] = __float_as_uint(__half2float(Xs[r * XPh + k0 + tig + 4]));
            a[mt][3] = __float_as_uint(__half2float(Xs[(r + 8) * XPh + k0 + tig + 4]));
        }
        uint32_t bf[WCT][2];
#pragma unroll
        for (int ct = 0; ct < WCT; ++ct) {
            int co = wc + ct * 8 + gid;
            bf[ct][0] = __float_as_uint(__half2float(Wt[(k0 + tig) * WPh + co]));
            bf[ct][1] = __float_as_uint(__half2float(Wt[(k0 + tig + 4) * WPh + co]));
        }
#pragma unroll
        for (int mt = 0; mt < 2; ++mt)
#pragma unroll
            for (int ct = 0; ct < WCT; ++ct)
                mma_tf32(acc[mt][ct], a[mt], bf[ct]);
    }

#pragma unroll
    for (int ct = 0; ct < WCT; ++ct) {
        float se = 0, so = 0, qe = 0, qo = 0;
#pragma unroll
        for (int mt = 0; mt < 2; ++mt) {
            const float* d = acc[mt][ct];
            se += d[0] + d[2]; so += d[1] + d[3];
            qe += d[0] * d[0] + d[2] * d[2];
            qo += d[1] * d[1] + d[3] * d[3];
        }
#pragma unroll
        for (int off = 16; off >= 4; off >>= 1) {
            se += __shfl_down_sync(0xffffffffu, se, off);
            so += __shfl_down_sync(0xffffffffu, so, off);
            qe += __shfl_down_sync(0xffffffffu, qe, off);
            qo += __shfl_down_sync(0xffffffffu, qo, off);
        }
        if (gid == 0) {
            int co = wc + ct * 8 + tig * 2;
            atomicAdd(&red[co], se);
            atomicAdd(&red[co + 1], so);
            atomicAdd(&red[COUT + co], qe);
            atomicAdd(&red[COUT + co + 1], qo);
        }
    }

    if (POOLK == 16) {
#pragma unroll
        for (int mt = 0; mt < 2; ++mt)
#pragma unroll
            for (int ct = 0; ct < WCT; ++ct) {
                const float* d = acc[mt][ct];
                float mxe = fmaxf(d[0], d[2]), mxo = fmaxf(d[1], d[3]);
                float mne = fminf(d[0], d[2]), mno = fminf(d[1], d[3]);
#pragma unroll
                for (int off = 16; off >= 4; off >>= 1) {
                    mxe = fmaxf(mxe, __shfl_down_sync(0xffffffffu, mxe, off));
                    mxo = fmaxf(mxo, __shfl_down_sync(0xffffffffu, mxo, off));
                    mne = fminf(mne, __shfl_down_sync(0xffffffffu, mne, off));
                    mno = fminf(mno, __shfl_down_sync(0xffffffffu, mno, off));
                }
                if (gid == 0) {
                    size_t g = (m0 + wm + mt * 16) >> 4;
                    int co = wc + ct * 8 + tig * 2;
                    *(float2*)(gmx + g * COUT + co) = make_float2(mxe, mxo);
                    *(float2*)(gmn + g * COUT + co) = make_float2(mne, mno);
                }
            }
    } else { // POOLK == 32
#pragma unroll
        for (int ct = 0; ct < WCT; ++ct) {
            float mxe = -1e30f, mxo = -1e30f, mne = 1e30f, mno = 1e30f;
#pragma unroll
            for (int mt = 0; mt < 2; ++mt) {
                const float* d = acc[mt][ct];
                mxe = fmaxf(mxe, fmaxf(d[0], d[2]));
                mxo = fmaxf(mxo, fmaxf(d[1], d[3]));
                mne = fminf(mne, fminf(d[0], d[2]));
                mno = fminf(mno, fminf(d[1], d[3]));
            }
#pragma unroll
            for (int off = 16; off >= 4; off >>= 1) {
                mxe = fmaxf(mxe, __shfl_down_sync(0xffffffffu, mxe, off));
                mxo = fmaxf(mxo, __shfl_down_sync(0xffffffffu, mxo, off));
                mne = fminf(mne, __shfl_down_sync(0xffffffffu, mne, off));
                mno = fminf(mno, __shfl_down_sync(0xffffffffu, mno, off));
            }
            if (gid == 0) {
                size_t g = (m0 + wm) >> 5;
                int co = wc + ct * 8 + tig * 2;
                *(float2*)(gmx + g * COUT + co) = make_float2(mxe, mxo);
                *(float2*)(gmn + g * COUT + co) = make_float2(mne, mno);
            }
        }
    }

    __syncthreads();
    if (tid < COUT) atomicAdd(&stats_out[tid], red[tid]);
    else if (tid < 2 * COUT) atomicAdd(&stats_out[128 + (tid - COUT)], red[tid]);
}

// ---------------- pooled affine+ReLU + transpose (consumer-side BN) ----------------
__global__ __launch_bounds__(256) void pool2_kernel(
    const float* __restrict__ gmx, const float* __restrict__ gmn,
    float* __restrict__ outfeat, int cbase,
    const float* __restrict__ stats_in, const float* __restrict__ gam,
    const float* __restrict__ bet, float invM)
{
    __shared__ float st[128][33];
    __shared__ float sa[128], sb2[128];
    const int b = blockIdx.y, s0 = blockIdx.x * 32;
    const int tid = threadIdx.x;
    if (tid < 128) {
        float mean = stats_in[tid] * invM;
        float var  = stats_in[128 + tid] * invM - mean * mean;
        float a = gam[tid] * rsqrtf(var + EPS_);
        sa[tid] = a;
        sb2[tid] = bet[tid] - mean * a;
    }
    __syncthreads();
    {
        int c = tid & 127, sh = tid >> 7;
        float a = sa[c], bb = sb2[c];
#pragma unroll
        for (int j = 0; j < 16; ++j) {
            int s = s0 + sh * 16 + j;
            size_t g = ((size_t)(b << 10) + s) * 128 + c;
            float v = (a > 0.0f) ? gmx[g] : gmn[g];
            st[c][sh * 16 + j] = fmaxf(fmaf(a, v, bb), 0.0f);
        }
    }
    __syncthreads();
    {
        int c = tid >> 1, part = tid & 1;
        float* dst = outfeat + (((size_t)(b * 256 + cbase + c)) << 10) + s0 + part * 16;
#pragma unroll
        for (int j = 0; j < 4; ++j) {
            int s = part * 16 + j * 4;
            *(float4*)(dst + j * 4) = make_float4(st[c][s], st[c][s + 1], st[c][s + 2], st[c][s + 3]);
        }
    }
}

// ---------------- host launch ----------------
extern "C" void kernel_launch(void* const* d_in, const int* in_sizes, int n_in,
                              void* d_out, int out_size)
{
    const float* xyz  = (const float*)d_in[0];
    const float* feat = (const float*)d_in[1];
    const float* w0[3] = { (const float*)d_in[2], (const float*)d_in[5], (const float*)d_in[8] };
    const float* g0[3] = { (const float*)d_in[3], (const float*)d_in[6], (const float*)d_in[9] };
    const float* b0[3] = { (const float*)d_in[4], (const float*)d_in[7], (const float*)d_in[10] };
    const float* w1[3] = { (const float*)d_in[11], (const float*)d_in[14], (const float*)d_in[17] };
    const float* g1[3] = { (const float*)d_in[12], (const float*)d_in[15], (const float*)d_in[18] };
    const float* b1[3] = { (const float*)d_in[13], (const float*)d_in[16], (const float*)d_in[19] };

    float* out = (float*)d_out;
    float* newxyz = out;
    float* outfeat = out + (size_t)B_ * S_ * 3;

    __half *b0buf, *b1buf, *fp0, *fp1;
    float *gmx0, *gmn0, *gmx1, *gmn1, *st6;
    int *idx0, *idx1;
    cudaGetSymbolAddress((void**)&b0buf, g_b0);
    cudaGetSymbolAddress((void**)&b1buf, g_b1);
    cudaGetSymbolAddress((void**)&fp0, g_fp0);
    cudaGetSymbolAddress((void**)&fp1, g_fp1);
    cudaGetSymbolAddress((void**)&gmx0, g_gmx0);
    cudaGetSymbolAddress((void**)&gmn0, g_gmn0);
    cudaGetSymbolAddress((void**)&gmx1, g_gmx1);
    cudaGetSymbolAddress((void**)&gmn1, g_gmn1);
    cudaGetSymbolAddress((void**)&st6, g_stats6);
    cudaGetSymbolAddress((void**)&idx0, g_idx0);
    cudaGetSymbolAddress((void**)&idx1, g_idx1);

    float* s0l0 = st6 + 0 * 256;  float* s0l1 = st6 + 1 * 256;  float* s0l2 = st6 + 2 * 256;
    float* s1l0 = st6 + 3 * 256;  float* s1l1 = st6 + 4 * 256;  float* s1l2 = st6 + 5 * 256;

    auto shb = [](int cin, int cout) {
        return cin * (cout + 8) * 2 + 128 * (cin + 8) * 2 + 2 * cout * 4;
    };
    const int fps_smem = 3 * N_ * 4;
    const int fg_smem = (64 * 65 + 64 * 128) * 4;

    static cudaStream_t sB = nullptr, sC = nullptr;
    static cudaEvent_t eRoot = nullptr, eFG = nullptr, eFPS = nullptr, eS1 = nullptr;
    if (!sB) {
        cudaStreamCreateWithFlags(&sB, cudaStreamNonBlocking);
        cudaStreamCreateWithFlags(&sC, cudaStreamNonBlocking);
        cudaEventCreateWithFlags(&eRoot, cudaEventDisableTiming);
        cudaEventCreateWithFlags(&eFG, cudaEventDisableTiming);
        cudaEventCreateWithFlags(&eFPS, cudaEventDisableTiming);
        cudaEventCreateWithFlags(&eS1, cudaEventDisableTiming);
        cudaFuncSetAttribute(mma_gather_kernel<64, 16>,  cudaFuncAttributeMaxDynamicSharedMemorySize, shb(64, 64));
        cudaFuncSetAttribute(mma_gather_kernel<96, 32>,  cudaFuncAttributeMaxDynamicSharedMemorySize, shb(64, 96));
        cudaFuncSetAttribute(mma_kernel<64, 128, 16>,    cudaFuncAttributeMaxDynamicSharedMemorySize, shb(64, 128));
        cudaFuncSetAttribute(mma_kernel<96, 128, 32>,    cudaFuncAttributeMaxDynamicSharedMemorySize, shb(96, 128));
        cudaFuncSetAttribute(featgemm2_kernel,           cudaFuncAttributeMaxDynamicSharedMemorySize, fg_smem);
        cudaFuncSetAttribute(fps_kernel,                 cudaFuncAttributeMaxDynamicSharedMemorySize, fps_smem);
    }

    // ---- capture fork: root event on the capture-origin stream ----
    cudaEventRecord(eRoot, 0);
    cudaStreamWaitEvent(sB, eRoot, 0);
    cudaStreamWaitEvent(sC, eRoot, 0);

    // stream B: zero stats + feature pre-GEMM (independent of FPS)
    zero6_kernel<<<1, 256, 0, sB>>>();
    featgemm2_kernel<<<dim3(N_ / 128, B_), 256, fg_smem, sB>>>(feat, w0[0], w1[0], fp0, fp1);
    cudaEventRecord(eFG, sB);

    // stream 0: FPS
    fps_kernel<<<B_, 1024, fps_smem>>>(xyz, newxyz);
    cudaEventRecord(eFPS, 0);

    // stream C: scale-1 chain
    cudaStreamWaitEvent(sC, eFPS, 0);
    ballquery1_kernel<K1_><<<dim3(S_ / 16, B_), 512, 0, sC>>>(xyz, newxyz, idx1, R1SQ);
    cudaStreamWaitEvent(sC, eFG, 0);
    stats0_kernel<K1_><<<M1_ / 128, 256, 0, sC>>>(xyz, newxyz, fp1, w1[0], idx1, s1l0);
    mma_gather_kernel<96, 32><<<M1_ / 128, 256, shb(64, 96), sC>>>(
        xyz, newxyz, fp1, w1[0], idx1, w1[1], b1buf, s1l0, g1[0], b1[0], 1.0f / M1_, s1l1);
    mma_kernel<96, 128, 32><<<M1_ / 128, 256, shb(96, 128), sC>>>(
        b1buf, w1[2], gmx1, gmn1, s1l1, g1[1], b1[1], 1.0f / M1_, s1l2);
    pool2_kernel<<<dim3(S_ / 32, B_), 256, 0, sC>>>(gmx1, gmn1, outfeat, 128, s1l2, g1[2], b1[2], 1.0f / M1_);
    cudaEventRecord(eS1, sC);

    // stream 0: scale-0 chain
    ballquery1_kernel<K0_><<<dim3(S_ / 16, B_), 512>>>(xyz, newxyz, idx0, R0SQ);
    cudaStreamWaitEvent(0, eFG, 0);
    stats0_kernel<K0_><<<M0_ / 128, 256>>>(xyz, newxyz, fp0, w0[0], idx0, s0l0);
    mma_gather_kernel<64, 16><<<M0_ / 128, 256, shb(64, 64)>>>(
        xyz, newxyz, fp0, w0[0], idx0, w0[1], b0buf, s0l0, g0[0], b0[0], 1.0f / M0_, s0l1);
    mma_kernel<64, 128, 16><<<M0_ / 128, 256, shb(64, 128)>>>(
        b0buf, w0[2], gmx0, gmn0, s0l1, g0[1], b0[1], 1.0f / M0_, s0l2);
    pool2_kernel<<<dim3(S_ / 32, B_), 256>>>(gmx0, gmn0, outfeat, 0, s0l2, g0[2], b0[2], 1.0f / M0_);

    // join side stream back into the capture-origin stream
    cudaStreamWaitEvent(0, eS1, 0);
}